// round 14
// baseline (speedup 1.0000x reference)
#include <cuda_runtime.h>
#include <cuda_bf16.h>
#include <cstdint>

// ---------------------------------------------------------------------------
// EMAVectorQuantizer on GB300 (compute_103 PTX -> HMMA via mma.sync):
// bf16 HMMA approximate GEMM (M=64 CTA tile, 2 CTAs/SM for 16 warps/SM)
// + candidate capture, exact fp32 rescoring (reference-bit chain), EMA update.
// ---------------------------------------------------------------------------

#define N_ROWS 16384
#define DDIM   512
#define KCODES 8192

#define OFF_Q  ((size_t)0)
#define OFF_T  ((size_t)8388608)
#define OFF_L  ((size_t)8404992)
#define OFF_E  ((size_t)8404993)
#define OFF_CS ((size_t)12599297)
#define OFF_W  ((size_t)12607489)

#define MARGIN 5e-4f
#define CBUF   4

__device__ __nv_bfloat16 g_ehi[(size_t)KCODES * DDIM];
__device__ float g_enorm[KCODES];
__device__ float g_xs[N_ROWS];
__device__ int   g_idx[N_ROWS];
__device__ int   g_cand[(size_t)N_ROWS * 32];
__device__ int   g_cnt[N_ROWS];
__device__ float g_sumsq;
__device__ float g_S;

// ---------------------------------------------------------------------------
__device__ __forceinline__ uint32_t packbf2(float lo, float hi) {
    __nv_bfloat162 h = __float22bfloat162_rn(make_float2(lo, hi));
    return *reinterpret_cast<uint32_t*>(&h);
}

__device__ __forceinline__ void mma16816(float& c0, float& c1, float& c2, float& c3,
                                         uint32_t a0, uint32_t a1, uint32_t a2,
                                         uint32_t a3, uint32_t b0, uint32_t b1) {
    asm volatile(
        "mma.sync.aligned.m16n8k16.row.col.f32.bf16.bf16.f32 "
        "{%0,%1,%2,%3}, {%4,%5,%6,%7}, {%8,%9}, {%0,%1,%2,%3};"
        : "+f"(c0), "+f"(c1), "+f"(c2), "+f"(c3)
        : "r"(a0), "r"(a1), "r"(a2), "r"(a3), "r"(b0), "r"(b1));
}

__device__ __forceinline__ uint32_t smem_u32(const void* p) {
    uint32_t a;
    asm("{ .reg .u64 t; cvta.to.shared.u64 t, %1; cvt.u32.u64 %0, t; }"
        : "=r"(a) : "l"(p));
    return a;
}

__device__ __forceinline__ void ldsm_x4(uint32_t& r0, uint32_t& r1,
                                        uint32_t& r2, uint32_t& r3, uint32_t a) {
    asm volatile("ldmatrix.sync.aligned.m8n8.x4.shared.b16 {%0,%1,%2,%3}, [%4];"
                 : "=r"(r0), "=r"(r1), "=r"(r2), "=r"(r3) : "r"(a));
}

// ---------------------------------------------------------------------------
// kernel: E -> bf16 + zero candidate counters
// ---------------------------------------------------------------------------
__global__ void k_splitE(const float* __restrict__ E) {
    size_t i = (size_t)blockIdx.x * blockDim.x + threadIdx.x;
    if (i < (size_t)KCODES * DDIM) g_ehi[i] = __float2bfloat16(E[i]);
    if (i < (size_t)N_ROWS) g_cnt[i] = 0;
}

// ---------------------------------------------------------------------------
// kernel: xs in XLA:CPU vectorized-reduce order (validated bit-exact)
// ---------------------------------------------------------------------------
__global__ void k_xnorm(const float* __restrict__ X) {
    int gid = blockIdx.x * blockDim.x + threadIdx.x;
    int n = gid >> 3;
    int l = gid & 7;
    if (n >= N_ROWS) return;
    const float* xr = X + (size_t)n * DDIM;
    float a = 0.0f;
#pragma unroll 8
    for (int t = 0; t < DDIM / 8; ++t) {
        float v = xr[t * 8 + l];
        a = __fadd_rn(a, __fmul_rn(v, v));
    }
    const unsigned m = 0xffffffffu;
    float b   = __shfl_down_sync(m, a, 4);
    float tot = __fadd_rn(a, b);
    float c   = __shfl_down_sync(m, tot, 2);
    float u   = __fadd_rn(tot, c);
    float d   = __shfl_down_sync(m, u, 1);
    float xs  = __fadd_rn(u, d);
    if (l == 0) g_xs[n] = xs;
}

// ---------------------------------------------------------------------------
// kernel: ||e||^2 (validated) + zero loss accumulator
// ---------------------------------------------------------------------------
__global__ void k_enorm(const float* __restrict__ E) {
    if (blockIdx.x == 0 && threadIdx.x == 0) g_sumsq = 0.0f;
    int warp = (blockIdx.x * blockDim.x + threadIdx.x) >> 5;
    int lane = threadIdx.x & 31;
    if (warp >= KCODES) return;
    const float4* p = reinterpret_cast<const float4*>(E + (size_t)warp * DDIM);
    float s = 0.0f;
#pragma unroll
    for (int i = 0; i < 4; ++i) {
        float4 v = p[lane + 32 * i];
        s += v.x * v.x + v.y * v.y + v.z * v.z + v.w * v.w;
    }
#pragma unroll
    for (int o = 16; o > 0; o >>= 1) s += __shfl_xor_sync(0xffffffffu, s, o);
    if (lane == 0) g_enorm[warp] = s;
}

// ---------------------------------------------------------------------------
// kernel: bf16 HMMA GEMM + approximate per-row argmin + candidate capture.
// CTA = 64 X-rows vs all 8192 codes; 8 warps as 2(M)x4(N): warp tile
// 32 rows x 32 cols. A fragment-major resident in SMEM (64KB); B double-
// buffered (2x18KB, one __syncthreads per 64-k chunk); B-frags via ldmatrix.
// 2 CTAs co-resident per SM (launch_bounds reg cap + 100KB SMEM).
// ---------------------------------------------------------------------------
#define SM_AF 0
#define SM_BS 65536
#define BSTG  18432
#define SMEM_HMMA (65536 + 2 * 18432)

__device__ __forceinline__ void upd_cand(float s, int col, float& rm, int& cnt,
                                         int* cc, float* cf) {
    if (s <= rm + MARGIN) {
        if (cnt == CBUF) {
            float thr = rm + MARGIN;
            int wp = 0;
#pragma unroll
            for (int i = 0; i < CBUF; ++i)
                if (cf[i] <= thr) { cc[wp] = cc[i]; cf[wp] = cf[i]; ++wp; }
            cnt = wp;
            if (cnt == CBUF) {
                int mi = 0;
#pragma unroll
                for (int i = 1; i < CBUF; ++i)
                    if (cf[i] > cf[mi]) mi = i;
                cnt = CBUF - 1;
                cc[mi] = cc[cnt]; cf[mi] = cf[cnt];
            }
        }
        cc[cnt] = col; cf[cnt] = s; ++cnt;
        if (s < rm) rm = s;
    }
}

__global__ void __launch_bounds__(256, 2) k_hmma(const float* __restrict__ X) {
    extern __shared__ __align__(16) char smem[];
    const uint32_t sb = smem_u32(smem);
    const int tid = threadIdx.x;
    const int w   = tid >> 5;
    const int l   = tid & 31;
    const int wm  = w >> 2;          // 0..1 : rows 32*wm .. 32*wm+31
    const int wn  = w & 3;           // 0..3 : cols 32*wn .. 32*wn+31
    const int m0  = blockIdx.x * 64;

    // ---- build A fragments (bf16) from fp32 X: 4 tiles of 16 rows
    for (int e = tid; e < 4096; e += 256) {
        int tw = e >> 10, rem = e & 1023, s = rem >> 5, ll = rem & 31;
        int r = m0 + tw * 16 + (ll >> 2);
        int k = s * 16 + 2 * (ll & 3);
        const float* x0 = X + (size_t)r * DDIM + k;
        float2 v00 = *reinterpret_cast<const float2*>(x0);
        float2 v10 = *reinterpret_cast<const float2*>(x0 + 8 * DDIM);
        float2 v01 = *reinterpret_cast<const float2*>(x0 + 8);
        float2 v11 = *reinterpret_cast<const float2*>(x0 + 8 * DDIM + 8);
        uint4 u;
        u.x = packbf2(v00.x, v00.y);
        u.y = packbf2(v10.x, v10.y);
        u.z = packbf2(v01.x, v01.y);
        u.w = packbf2(v11.x, v11.y);
        *reinterpret_cast<uint4*>(smem + SM_AF + (size_t)e * 16) = u;
    }

    // ---- B global prefetch into registers (full 128-col x 64-k chunk)
    uint4 pb[4];
    auto LDB = [&](int nt, int kc) {
#pragma unroll
        for (int i = 0; i < 4; ++i) {
            int f = tid + 256 * i;
            int row = f >> 3, q = f & 7;
            pb[i] = *reinterpret_cast<const uint4*>(
                reinterpret_cast<const char*>(g_ehi) +
                (size_t)(nt * 128 + row) * 1024 + kc * 128 + q * 16);
        }
    };
    auto STB = [&](int stg) {
        char* base = smem + SM_BS + stg * BSTG;
#pragma unroll
        for (int i = 0; i < 4; ++i) {
            int f = tid + 256 * i;
            int row = f >> 3, q = f & 7;
            *reinterpret_cast<uint4*>(base + row * 144 + q * 16) = pb[i];
        }
    };

    LDB(0, 0);
    STB(0);
    __syncthreads();    // A fragments + stage0 visible
    LDB(0, 1);

    // per-lane candidate state for 4 rows: R[b] = m0 + 32*wm + 8*b + (l>>2)
    float rm[4];
    int   cnt4[4];
    int   cc[4][CBUF];
    float cf[4][CBUF];
#pragma unroll
    for (int b = 0; b < 4; ++b) { rm[b] = __int_as_float(0x7f800000); cnt4[b] = 0; }

    // ldmatrix lane address pieces: tile t = l>>3 -> col 8*(t>>1)+(l&7),
    // k-offset (t&1)*16 bytes
    const int bt      = l >> 3;
    const int bcol    = ((bt >> 1) << 3) + (l & 7);
    const int bkoff16 = (bt & 1) * 16;
    const uint32_t baddr0 = sb + SM_BS + (wn * 32 + bcol) * 144 + bkoff16;

    for (int nt = 0; nt < KCODES / 128; ++nt) {
        float acc[2][4][4];
#pragma unroll
        for (int t = 0; t < 2; ++t)
#pragma unroll
            for (int g = 0; g < 4; ++g)
#pragma unroll
                for (int q = 0; q < 4; ++q) acc[t][g][q] = 0.0f;

        for (int kc = 0; kc < 8; ++kc) {
            const int seg = nt * 8 + kc;
            const int stg = seg & 1;
            const uint32_t bstg = baddr0 + stg * BSTG;

#pragma unroll
            for (int s = 0; s < 4; ++s) {
                uint4 af0 = *reinterpret_cast<const uint4*>(
                    smem + SM_AF + (size_t)(((2 * wm) * 32 + (kc * 4 + s)) * 32 + l) * 16);
                uint4 af1 = *reinterpret_cast<const uint4*>(
                    smem + SM_AF + (size_t)(((2 * wm + 1) * 32 + (kc * 4 + s)) * 32 + l) * 16);
                uint32_t bw[4][2];
#pragma unroll
                for (int gp = 0; gp < 2; ++gp) {
                    uint32_t r0, r1, r2, r3;
                    ldsm_x4(r0, r1, r2, r3, bstg + (gp * 16) * 144 + s * 32);
                    bw[2 * gp][0] = r0; bw[2 * gp][1] = r1;
                    bw[2 * gp + 1][0] = r2; bw[2 * gp + 1][1] = r3;
                }
#pragma unroll
                for (int g = 0; g < 4; ++g) {
                    mma16816(acc[0][g][0], acc[0][g][1], acc[0][g][2], acc[0][g][3],
                             af0.x, af0.y, af0.z, af0.w, bw[g][0], bw[g][1]);
                    mma16816(acc[1][g][0], acc[1][g][1], acc[1][g][2], acc[1][g][3],
                             af1.x, af1.y, af1.z, af1.w, bw[g][0], bw[g][1]);
                }
            }
            if (seg + 1 < 512) STB((seg + 1) & 1);
            __syncthreads();
            {
                int s2 = seg + 2;
                if (s2 < 512) LDB(s2 >> 3, s2 & 7);
            }
        }

        // epilogue: s~ = en - 2*dot (xs constant per row); capture candidates
#pragma unroll
        for (int g = 0; g < 4; ++g) {
            int col0 = nt * 128 + wn * 32 + g * 8 + 2 * (l & 3);
            float2 en = __ldg(reinterpret_cast<const float2*>(g_enorm + col0));
#pragma unroll
            for (int t = 0; t < 2; ++t) {
                float s00 = fmaf(-2.0f, acc[t][g][0], en.x);
                float s01 = fmaf(-2.0f, acc[t][g][1], en.y);
                float s10 = fmaf(-2.0f, acc[t][g][2], en.x);
                float s11 = fmaf(-2.0f, acc[t][g][3], en.y);
                upd_cand(s00, col0,     rm[2 * t],     cnt4[2 * t],     cc[2 * t],     cf[2 * t]);
                upd_cand(s01, col0 + 1, rm[2 * t],     cnt4[2 * t],     cc[2 * t],     cf[2 * t]);
                upd_cand(s10, col0,     rm[2 * t + 1], cnt4[2 * t + 1], cc[2 * t + 1], cf[2 * t + 1]);
                upd_cand(s11, col0 + 1, rm[2 * t + 1], cnt4[2 * t + 1], cc[2 * t + 1], cf[2 * t + 1]);
            }
        }
    }

    // finalize: per-row min over the 4 lanes sharing a row, filter, append
#pragma unroll
    for (int b = 0; b < 4; ++b) {
        float gm = rm[b];
        gm = fminf(gm, __shfl_xor_sync(0xffffffffu, gm, 1));
        gm = fminf(gm, __shfl_xor_sync(0xffffffffu, gm, 2));
        float thr = gm + MARGIN;
        int kept = 0, tmp[CBUF];
#pragma unroll
        for (int i = 0; i < CBUF; ++i)
            if (i < cnt4[b] && cf[b][i] <= thr) tmp[kept++] = cc[b][i];
        if (kept) {
            int row = m0 + 32 * wm + 8 * b + (l >> 2);
            int base = atomicAdd(&g_cnt[row], kept);
            for (int i = 0; i < kept; ++i)
                if (base + i < 32) g_cand[(size_t)row * 32 + base + i] = tmp[i];
        }
    }
}

// ---------------------------------------------------------------------------
// kernel: exact rescoring (R5-validated chain: sequential-k single-acc fma,
// fl(fl(xs-2dot)+en), ties -> lowest index)
// ---------------------------------------------------------------------------
__global__ void __launch_bounds__(32) k_rescore(const float* __restrict__ X,
                                                const float* __restrict__ E) {
    __shared__ float sx[DDIM];
    const int row = blockIdx.x;
    const int t   = threadIdx.x;
    const float4* xr = reinterpret_cast<const float4*>(X + (size_t)row * DDIM);
#pragma unroll
    for (int r = 0; r < 4; ++r)
        reinterpret_cast<float4*>(sx)[t + 32 * r] = xr[t + 32 * r];
    __syncwarp();

    int cnt = g_cnt[row];
    if (cnt > 32) cnt = 32;
    float s  = __int_as_float(0x7f800000);
    int  col = 0x7fffffff;
    if (t < cnt) {
        col = g_cand[(size_t)row * 32 + t];
        const float* er = E + (size_t)col * DDIM;
        float acc = 0.0f;
#pragma unroll 8
        for (int k = 0; k < DDIM; ++k) acc = __fmaf_rn(sx[k], er[k], acc);
        s = __fadd_rn(__fadd_rn(g_xs[row], -2.0f * acc), g_enorm[col]);
    }
#pragma unroll
    for (int o = 16; o > 0; o >>= 1) {
        float vs = __shfl_down_sync(0xffffffffu, s, o);
        int   vc = __shfl_down_sync(0xffffffffu, col, o);
        if (vs < s || (vs == s && vc < col)) { s = vs; col = vc; }
    }
    if (t == 0) g_idx[row] = col;
}

// ---------------------------------------------------------------------------
// EMA update kernels (validated)
// ---------------------------------------------------------------------------
__global__ void k_init(const float* __restrict__ ew,
                       const float* __restrict__ ecs,
                       float* __restrict__ out) {
    size_t i = (size_t)blockIdx.x * blockDim.x + threadIdx.x;
    if (i < (size_t)KCODES * DDIM) out[OFF_W + i] = 0.99f * ew[i];
    if (i < (size_t)KCODES)        out[OFF_CS + i] = 0.99f * ecs[i];
}

__global__ void __launch_bounds__(128)
k_gather(const float* __restrict__ X, const float* __restrict__ E,
         float* __restrict__ out) {
    const int n   = blockIdx.x;
    const int t   = threadIdx.x;
    const int idx = g_idx[n];
    const float4 f = reinterpret_cast<const float4*>(X + (size_t)n * DDIM)[t];
    const float4 e = reinterpret_cast<const float4*>(E + (size_t)idx * DDIM)[t];
    float4 q;
    q.x = f.x + (e.x - f.x);
    q.y = f.y + (e.y - f.y);
    q.z = f.z + (e.z - f.z);
    q.w = f.w + (e.w - f.w);
    reinterpret_cast<float4*>(out + OFF_Q + (size_t)n * DDIM)[t] = q;
    float dx = f.x - q.x, dy = f.y - q.y, dz = f.z - q.z, dw = f.w - q.w;
    float local = dx * dx + dy * dy + dz * dz + dw * dw;

    const float om = (float)(1.0 - 0.99);
    float* wv = out + OFF_W + (size_t)idx * DDIM + (size_t)t * 4;
    atomicAdd(wv + 0, om * f.x);
    atomicAdd(wv + 1, om * f.y);
    atomicAdd(wv + 2, om * f.z);
    atomicAdd(wv + 3, om * f.w);

    __shared__ float red[128];
    red[t] = local;
    __syncthreads();
#pragma unroll
    for (int o = 64; o > 0; o >>= 1) {
        if (t < o) red[t] += red[t + o];
        __syncthreads();
    }
    if (t == 0) {
        atomicAdd(&g_sumsq, red[0]);
        out[OFF_T + n] = (float)idx;
        atomicAdd(out + OFF_CS + idx, om);
    }
}

__global__ void k_sumcs(const float* __restrict__ cs) {
    __shared__ float red[256];
    float s = 0.0f;
    for (int i = threadIdx.x; i < KCODES; i += 256) s += cs[i];
    red[threadIdx.x] = s;
    __syncthreads();
#pragma unroll
    for (int o = 128; o > 0; o >>= 1) {
        if (threadIdx.x < o) red[threadIdx.x] += red[threadIdx.x + o];
        __syncthreads();
    }
    if (threadIdx.x == 0) g_S = red[0];
}

__global__ void k_final(float* __restrict__ out) {
    size_t i = (size_t)blockIdx.x * blockDim.x + threadIdx.x;
    if (i == 0) out[OFF_L] = 0.25f * (g_sumsq / 8388608.0f);
    if (i >= (size_t)KCODES * DDIM) return;
    size_t k = i >> 9;
    float csn = (out[OFF_CS + k] + 1e-5f) / (g_S + (float)(8192 * 1e-5));
    out[OFF_E + i] = out[OFF_W + i] / csn;
}

// ---------------------------------------------------------------------------
extern "C" void kernel_launch(void* const* d_in, const int* in_sizes, int n_in,
                              void* d_out, int out_size) {
    const float* X   = (const float*)d_in[0];
    const float* E   = (const float*)d_in[1];
    const float* ecs = (const float*)d_in[2];
    const float* ew  = (const float*)d_in[3];
    float* out = (float*)d_out;

    cudaFuncSetAttribute(k_hmma, cudaFuncAttributeMaxDynamicSharedMemorySize,
                         SMEM_HMMA);

    k_splitE <<<(KCODES * DDIM + 255) / 256, 256>>>(E);
    k_xnorm  <<<N_ROWS * 8 / 256, 256>>>(X);
    k_enorm  <<<KCODES / 8, 256>>>(E);
    k_hmma   <<<N_ROWS / 64, 256, SMEM_HMMA>>>(X);
    k_rescore<<<N_ROWS, 32>>>(X, E);
    k_init   <<<(KCODES * DDIM + 255) / 256, 256>>>(ew, ecs, out);
    k_gather <<<N_ROWS, 128>>>(X, E, out);
    k_sumcs  <<<1, 256>>>(out + OFF_CS);
    k_final  <<<(KCODES * DDIM + 255) / 256, 256>>>(out);
}

// round 15
// speedup vs baseline: 1.0465x; 1.0465x over previous
#include <cuda_runtime.h>
#include <cuda_bf16.h>
#include <cstdint>

// ---------------------------------------------------------------------------
// EMAVectorQuantizer on GB300 (compute_103 PTX -> HMMA via mma.sync):
// bf16 HMMA approximate GEMM with cp.async 3-stage B pipeline (latency
// decoupled), candidate capture, exact fp32 rescoring (reference-bit chain),
// then EMA update.
// ---------------------------------------------------------------------------

#define N_ROWS 16384
#define DDIM   512
#define KCODES 8192

#define OFF_Q  ((size_t)0)
#define OFF_T  ((size_t)8388608)
#define OFF_L  ((size_t)8404992)
#define OFF_E  ((size_t)8404993)
#define OFF_CS ((size_t)12599297)
#define OFF_W  ((size_t)12607489)

#define MARGIN 5e-4f
#define CBUF   4

__device__ __nv_bfloat16 g_ehi[(size_t)KCODES * DDIM];
__device__ float g_enorm[KCODES];
__device__ float g_xs[N_ROWS];
__device__ int   g_idx[N_ROWS];
__device__ int   g_cand[(size_t)N_ROWS * 32];
__device__ int   g_cnt[N_ROWS];
__device__ float g_sumsq;
__device__ float g_S;

// ---------------------------------------------------------------------------
__device__ __forceinline__ uint32_t packbf2(float lo, float hi) {
    __nv_bfloat162 h = __float22bfloat162_rn(make_float2(lo, hi));
    return *reinterpret_cast<uint32_t*>(&h);
}

__device__ __forceinline__ void mma16816(float& c0, float& c1, float& c2, float& c3,
                                         uint32_t a0, uint32_t a1, uint32_t a2,
                                         uint32_t a3, uint32_t b0, uint32_t b1) {
    asm volatile(
        "mma.sync.aligned.m16n8k16.row.col.f32.bf16.bf16.f32 "
        "{%0,%1,%2,%3}, {%4,%5,%6,%7}, {%8,%9}, {%0,%1,%2,%3};"
        : "+f"(c0), "+f"(c1), "+f"(c2), "+f"(c3)
        : "r"(a0), "r"(a1), "r"(a2), "r"(a3), "r"(b0), "r"(b1));
}

__device__ __forceinline__ uint32_t smem_u32(const void* p) {
    uint32_t a;
    asm("{ .reg .u64 t; cvta.to.shared.u64 t, %1; cvt.u32.u64 %0, t; }"
        : "=r"(a) : "l"(p));
    return a;
}

__device__ __forceinline__ void ldsm_x4(uint32_t& r0, uint32_t& r1,
                                        uint32_t& r2, uint32_t& r3, uint32_t a) {
    asm volatile("ldmatrix.sync.aligned.m8n8.x4.shared.b16 {%0,%1,%2,%3}, [%4];"
                 : "=r"(r0), "=r"(r1), "=r"(r2), "=r"(r3) : "r"(a));
}

__device__ __forceinline__ void cp_async16(uint32_t dst, const void* src) {
    asm volatile("cp.async.cg.shared.global [%0], [%1], 16;"
                 :: "r"(dst), "l"(src) : "memory");
}
#define CP_COMMIT() asm volatile("cp.async.commit_group;" ::: "memory")
#define CP_WAIT1()  asm volatile("cp.async.wait_group 1;" ::: "memory")
#define CP_WAIT0()  asm volatile("cp.async.wait_group 0;" ::: "memory")

// ---------------------------------------------------------------------------
// kernel: E -> bf16 + zero candidate counters
// ---------------------------------------------------------------------------
__global__ void k_splitE(const float* __restrict__ E) {
    size_t i = (size_t)blockIdx.x * blockDim.x + threadIdx.x;
    if (i < (size_t)KCODES * DDIM) g_ehi[i] = __float2bfloat16(E[i]);
    if (i < (size_t)N_ROWS) g_cnt[i] = 0;
}

// ---------------------------------------------------------------------------
// kernel: xs in XLA:CPU vectorized-reduce order (validated bit-exact)
// ---------------------------------------------------------------------------
__global__ void k_xnorm(const float* __restrict__ X) {
    int gid = blockIdx.x * blockDim.x + threadIdx.x;
    int n = gid >> 3;
    int l = gid & 7;
    if (n >= N_ROWS) return;
    const float* xr = X + (size_t)n * DDIM;
    float a = 0.0f;
#pragma unroll 8
    for (int t = 0; t < DDIM / 8; ++t) {
        float v = xr[t * 8 + l];
        a = __fadd_rn(a, __fmul_rn(v, v));
    }
    const unsigned m = 0xffffffffu;
    float b   = __shfl_down_sync(m, a, 4);
    float tot = __fadd_rn(a, b);
    float c   = __shfl_down_sync(m, tot, 2);
    float u   = __fadd_rn(tot, c);
    float d   = __shfl_down_sync(m, u, 1);
    float xs  = __fadd_rn(u, d);
    if (l == 0) g_xs[n] = xs;
}

// ---------------------------------------------------------------------------
// kernel: ||e||^2 (validated) + zero loss accumulator
// ---------------------------------------------------------------------------
__global__ void k_enorm(const float* __restrict__ E) {
    if (blockIdx.x == 0 && threadIdx.x == 0) g_sumsq = 0.0f;
    int warp = (blockIdx.x * blockDim.x + threadIdx.x) >> 5;
    int lane = threadIdx.x & 31;
    if (warp >= KCODES) return;
    const float4* p = reinterpret_cast<const float4*>(E + (size_t)warp * DDIM);
    float s = 0.0f;
#pragma unroll
    for (int i = 0; i < 4; ++i) {
        float4 v = p[lane + 32 * i];
        s += v.x * v.x + v.y * v.y + v.z * v.z + v.w * v.w;
    }
#pragma unroll
    for (int o = 16; o > 0; o >>= 1) s += __shfl_xor_sync(0xffffffffu, s, o);
    if (lane == 0) g_enorm[warp] = s;
}

// ---------------------------------------------------------------------------
// kernel: bf16 HMMA GEMM + approximate per-row argmin + candidate capture.
// CTA = 64 X-rows vs all 8192 codes; 8 warps as 2(M)x4(N), warp tile 32x32.
// A fragment-major resident in SMEM (64KB). B: cp.async 3-stage ring of
// 16KB swizzled stages (2 chunks always in flight -> L2 latency decoupled).
// 2 CTAs/SM (114688B SMEM each, reg cap via launch_bounds).
// ---------------------------------------------------------------------------
#define SM_AF 0
#define SM_BS 65536
#define BSTG  16384
#define SMEM_HMMA (65536 + 3 * 16384)

__device__ __forceinline__ void upd_cand(float s, int col, float& rm, int& cnt,
                                         int* cc, float* cf) {
    if (s <= rm + MARGIN) {
        if (cnt == CBUF) {
            float thr = rm + MARGIN;
            int wp = 0;
#pragma unroll
            for (int i = 0; i < CBUF; ++i)
                if (cf[i] <= thr) { cc[wp] = cc[i]; cf[wp] = cf[i]; ++wp; }
            cnt = wp;
            if (cnt == CBUF) {
                int mi = 0;
#pragma unroll
                for (int i = 1; i < CBUF; ++i)
                    if (cf[i] > cf[mi]) mi = i;
                cnt = CBUF - 1;
                cc[mi] = cc[cnt]; cf[mi] = cf[cnt];
            }
        }
        cc[cnt] = col; cf[cnt] = s; ++cnt;
        if (s < rm) rm = s;
    }
}

__global__ void __launch_bounds__(256, 2) k_hmma(const float* __restrict__ X) {
    extern __shared__ __align__(16) char smem[];
    const uint32_t sb = smem_u32(smem);
    const int tid = threadIdx.x;
    const int w   = tid >> 5;
    const int l   = tid & 31;
    const int wm  = w >> 2;          // 0..1 : rows 32*wm .. 32*wm+31
    const int wn  = w & 3;           // 0..3 : cols 32*wn .. 32*wn+31
    const int m0  = blockIdx.x * 64;

    // cp.async fill of one 64-k B chunk into stage (seg%3), swizzled:
    //   dst 16B-chunk index q' = q ^ (col & 7)
    auto FILL = [&](int seg) {
        const int nt = seg >> 3, kc = seg & 7;
        const uint32_t stage = sb + SM_BS + (seg % 3) * BSTG;
        const char* srcb = reinterpret_cast<const char*>(g_ehi) +
                           (size_t)(nt * 128) * 1024 + kc * 128;
#pragma unroll
        for (int i = 0; i < 4; ++i) {
            int f = tid + 256 * i;
            int row = f >> 3, q = f & 7;
            cp_async16(stage + row * 128 + ((q ^ (row & 7)) << 4),
                       srcb + (size_t)row * 1024 + q * 16);
        }
        CP_COMMIT();
    };

    FILL(0);
    FILL(1);

    // ---- build A fragments (bf16) from fp32 X: 4 tiles of 16 rows
    for (int e = tid; e < 4096; e += 256) {
        int tw = e >> 10, rem = e & 1023, s = rem >> 5, ll = rem & 31;
        int r = m0 + tw * 16 + (ll >> 2);
        int k = s * 16 + 2 * (ll & 3);
        const float* x0 = X + (size_t)r * DDIM + k;
        float2 v00 = *reinterpret_cast<const float2*>(x0);
        float2 v10 = *reinterpret_cast<const float2*>(x0 + 8 * DDIM);
        float2 v01 = *reinterpret_cast<const float2*>(x0 + 8);
        float2 v11 = *reinterpret_cast<const float2*>(x0 + 8 * DDIM + 8);
        uint4 u;
        u.x = packbf2(v00.x, v00.y);
        u.y = packbf2(v10.x, v10.y);
        u.z = packbf2(v01.x, v01.y);
        u.w = packbf2(v11.x, v11.y);
        *reinterpret_cast<uint4*>(smem + SM_AF + (size_t)e * 16) = u;
    }

    // per-lane candidate state for 4 rows: R[b] = m0 + 32*wm + 8*b + (l>>2)
    float rm[4];
    int   cnt4[4];
    int   cc[4][CBUF];
    float cf[4][CBUF];
#pragma unroll
    for (int b = 0; b < 4; ++b) { rm[b] = __int_as_float(0x7f800000); cnt4[b] = 0; }

    // ldmatrix lane pieces: bt = l>>3; col-in-16 = (bt>>1)*8 + (l&7);
    // k-chunk low bit = bt&1; swizzle XOR term = l&7 (col&7 invariant mod 16)
    const int bt   = l >> 3;
    const int bcol = ((bt >> 1) << 3) + (l & 7);
    const int kb1  = bt & 1;
    const int l7   = l & 7;
    const uint32_t colbase = (wn * 32 + bcol) * 128;  // within stage

    float acc[2][4][4];

    for (int seg = 0; seg < 512; ++seg) {
        const int nt = seg >> 3, kc = seg & 7;
        if (kc == 0) {
#pragma unroll
            for (int t = 0; t < 2; ++t)
#pragma unroll
                for (int g = 0; g < 4; ++g)
#pragma unroll
                    for (int q = 0; q < 4; ++q) acc[t][g][q] = 0.0f;
        }

        CP_WAIT1();          // own copies of fill(seg) landed
        __syncthreads();     // cross-thread visibility; stage (seg+2)%3 free
        if (seg + 2 < 512) FILL(seg + 2);

        const uint32_t bstage = sb + SM_BS + (seg % 3) * BSTG;

#pragma unroll
        for (int s = 0; s < 4; ++s) {
            uint4 af0 = *reinterpret_cast<const uint4*>(
                smem + SM_AF + (size_t)(((2 * wm) * 32 + (kc * 4 + s)) * 32 + l) * 16);
            uint4 af1 = *reinterpret_cast<const uint4*>(
                smem + SM_AF + (size_t)(((2 * wm + 1) * 32 + (kc * 4 + s)) * 32 + l) * 16);
            const uint32_t ksw = (uint32_t)(((s << 1) | kb1) ^ l7) << 4;
            uint32_t bw[4][2];
#pragma unroll
            for (int gp = 0; gp < 2; ++gp) {
                uint32_t r0, r1, r2, r3;
                ldsm_x4(r0, r1, r2, r3, bstage + colbase + gp * (16 * 128) + ksw);
                bw[2 * gp][0] = r0; bw[2 * gp][1] = r1;
                bw[2 * gp + 1][0] = r2; bw[2 * gp + 1][1] = r3;
            }
#pragma unroll
            for (int g = 0; g < 4; ++g) {
                mma16816(acc[0][g][0], acc[0][g][1], acc[0][g][2], acc[0][g][3],
                         af0.x, af0.y, af0.z, af0.w, bw[g][0], bw[g][1]);
                mma16816(acc[1][g][0], acc[1][g][1], acc[1][g][2], acc[1][g][3],
                         af1.x, af1.y, af1.z, af1.w, bw[g][0], bw[g][1]);
            }
        }

        if (kc == 7) {
            // epilogue: s~ = en - 2*dot (xs constant per row); capture
#pragma unroll
            for (int g = 0; g < 4; ++g) {
                int col0 = nt * 128 + wn * 32 + g * 8 + 2 * (l & 3);
                float2 en = __ldg(reinterpret_cast<const float2*>(g_enorm + col0));
#pragma unroll
                for (int t = 0; t < 2; ++t) {
                    float s00 = fmaf(-2.0f, acc[t][g][0], en.x);
                    float s01 = fmaf(-2.0f, acc[t][g][1], en.y);
                    float s10 = fmaf(-2.0f, acc[t][g][2], en.x);
                    float s11 = fmaf(-2.0f, acc[t][g][3], en.y);
                    upd_cand(s00, col0,     rm[2 * t],     cnt4[2 * t],     cc[2 * t],     cf[2 * t]);
                    upd_cand(s01, col0 + 1, rm[2 * t],     cnt4[2 * t],     cc[2 * t],     cf[2 * t]);
                    upd_cand(s10, col0,     rm[2 * t + 1], cnt4[2 * t + 1], cc[2 * t + 1], cf[2 * t + 1]);
                    upd_cand(s11, col0 + 1, rm[2 * t + 1], cnt4[2 * t + 1], cc[2 * t + 1], cf[2 * t + 1]);
                }
            }
        }
    }
    CP_WAIT0();

    // finalize: per-row min over the 4 lanes sharing a row, filter, append
#pragma unroll
    for (int b = 0; b < 4; ++b) {
        float gm = rm[b];
        gm = fminf(gm, __shfl_xor_sync(0xffffffffu, gm, 1));
        gm = fminf(gm, __shfl_xor_sync(0xffffffffu, gm, 2));
        float thr = gm + MARGIN;
        int kept = 0, tmp[CBUF];
#pragma unroll
        for (int i = 0; i < CBUF; ++i)
            if (i < cnt4[b] && cf[b][i] <= thr) tmp[kept++] = cc[b][i];
        if (kept) {
            int row = m0 + 32 * wm + 8 * b + (l >> 2);
            int base = atomicAdd(&g_cnt[row], kept);
            for (int i = 0; i < kept; ++i)
                if (base + i < 32) g_cand[(size_t)row * 32 + base + i] = tmp[i];
        }
    }
}

// ---------------------------------------------------------------------------
// kernel: exact rescoring (R5-validated chain: sequential-k single-acc fma,
// fl(fl(xs-2dot)+en), ties -> lowest index)
// ---------------------------------------------------------------------------
__global__ void __launch_bounds__(32) k_rescore(const float* __restrict__ X,
                                                const float* __restrict__ E) {
    __shared__ float sx[DDIM];
    const int row = blockIdx.x;
    const int t   = threadIdx.x;
    const float4* xr = reinterpret_cast<const float4*>(X + (size_t)row * DDIM);
#pragma unroll
    for (int r = 0; r < 4; ++r)
        reinterpret_cast<float4*>(sx)[t + 32 * r] = xr[t + 32 * r];
    __syncwarp();

    int cnt = g_cnt[row];
    if (cnt > 32) cnt = 32;
    float s  = __int_as_float(0x7f800000);
    int  col = 0x7fffffff;
    if (t < cnt) {
        col = g_cand[(size_t)row * 32 + t];
        const float* er = E + (size_t)col * DDIM;
        float acc = 0.0f;
#pragma unroll 8
        for (int k = 0; k < DDIM; ++k) acc = __fmaf_rn(sx[k], er[k], acc);
        s = __fadd_rn(__fadd_rn(g_xs[row], -2.0f * acc), g_enorm[col]);
    }
#pragma unroll
    for (int o = 16; o > 0; o >>= 1) {
        float vs = __shfl_down_sync(0xffffffffu, s, o);
        int   vc = __shfl_down_sync(0xffffffffu, col, o);
        if (vs < s || (vs == s && vc < col)) { s = vs; col = vc; }
    }
    if (t == 0) g_idx[row] = col;
}

// ---------------------------------------------------------------------------
// EMA update kernels (validated)
// ---------------------------------------------------------------------------
__global__ void k_init(const float* __restrict__ ew,
                       const float* __restrict__ ecs,
                       float* __restrict__ out) {
    size_t i = (size_t)blockIdx.x * blockDim.x + threadIdx.x;
    if (i < (size_t)KCODES * DDIM) out[OFF_W + i] = 0.99f * ew[i];
    if (i < (size_t)KCODES)        out[OFF_CS + i] = 0.99f * ecs[i];
}

__global__ void __launch_bounds__(128)
k_gather(const float* __restrict__ X, const float* __restrict__ E,
         float* __restrict__ out) {
    const int n   = blockIdx.x;
    const int t   = threadIdx.x;
    const int idx = g_idx[n];
    const float4 f = reinterpret_cast<const float4*>(X + (size_t)n * DDIM)[t];
    const float4 e = reinterpret_cast<const float4*>(E + (size_t)idx * DDIM)[t];
    float4 q;
    q.x = f.x + (e.x - f.x);
    q.y = f.y + (e.y - f.y);
    q.z = f.z + (e.z - f.z);
    q.w = f.w + (e.w - f.w);
    reinterpret_cast<float4*>(out + OFF_Q + (size_t)n * DDIM)[t] = q;
    float dx = f.x - q.x, dy = f.y - q.y, dz = f.z - q.z, dw = f.w - q.w;
    float local = dx * dx + dy * dy + dz * dz + dw * dw;

    const float om = (float)(1.0 - 0.99);
    float* wv = out + OFF_W + (size_t)idx * DDIM + (size_t)t * 4;
    atomicAdd(wv + 0, om * f.x);
    atomicAdd(wv + 1, om * f.y);
    atomicAdd(wv + 2, om * f.z);
    atomicAdd(wv + 3, om * f.w);

    __shared__ float red[128];
    red[t] = local;
    __syncthreads();
#pragma unroll
    for (int o = 64; o > 0; o >>= 1) {
        if (t < o) red[t] += red[t + o];
        __syncthreads();
    }
    if (t == 0) {
        atomicAdd(&g_sumsq, red[0]);
        out[OFF_T + n] = (float)idx;
        atomicAdd(out + OFF_CS + idx, om);
    }
}

__global__ void k_sumcs(const float* __restrict__ cs) {
    __shared__ float red[256];
    float s = 0.0f;
    for (int i = threadIdx.x; i < KCODES; i += 256) s += cs[i];
    red[threadIdx.x] = s;
    __syncthreads();
#pragma unroll
    for (int o = 128; o > 0; o >>= 1) {
        if (threadIdx.x < o) red[threadIdx.x] += red[threadIdx.x + o];
        __syncthreads();
    }
    if (threadIdx.x == 0) g_S = red[0];
}

__global__ void k_final(float* __restrict__ out) {
    size_t i = (size_t)blockIdx.x * blockDim.x + threadIdx.x;
    if (i == 0) out[OFF_L] = 0.25f * (g_sumsq / 8388608.0f);
    if (i >= (size_t)KCODES * DDIM) return;
    size_t k = i >> 9;
    float csn = (out[OFF_CS + k] + 1e-5f) / (g_S + (float)(8192 * 1e-5));
    out[OFF_E + i] = out[OFF_W + i] / csn;
}

// ---------------------------------------------------------------------------
extern "C" void kernel_launch(void* const* d_in, const int* in_sizes, int n_in,
                              void* d_out, int out_size) {
    const float* X   = (const float*)d_in[0];
    const float* E   = (const float*)d_in[1];
    const float* ecs = (const float*)d_in[2];
    const float* ew  = (const float*)d_in[3];
    float* out = (float*)d_out;

    cudaFuncSetAttribute(k_hmma, cudaFuncAttributeMaxDynamicSharedMemorySize,
                         SMEM_HMMA);

    k_splitE <<<(KCODES * DDIM + 255) / 256, 256>>>(E);
    k_xnorm  <<<N_ROWS * 8 / 256, 256>>>(X);
    k_enorm  <<<KCODES / 8, 256>>>(E);
    k_hmma   <<<N_ROWS / 64, 256, SMEM_HMMA>>>(X);
    k_rescore<<<N_ROWS, 32>>>(X, E);
    k_init   <<<(KCODES * DDIM + 255) / 256, 256>>>(ew, ecs, out);
    k_gather <<<N_ROWS, 128>>>(X, E, out);
    k_sumcs  <<<1, 256>>>(out + OFF_CS);
    k_final  <<<(KCODES * DDIM + 255) / 256, 256>>>(out);
}

// round 16
// speedup vs baseline: 1.1412x; 1.0906x over previous
#include <cuda_runtime.h>
#include <cuda_bf16.h>
#include <cstdint>

// ---------------------------------------------------------------------------
// EMAVectorQuantizer on GB300 (compute_103 PTX -> HMMA via mma.sync):
// bf16 HMMA approximate GEMM, cp.async 3-stage B ring, 512-thr CTAs with
// warp tile 16x32 -> 32 warps/SM (occ 50%); candidate capture + exact fp32
// rescoring (reference-bit chain), then EMA update.
// ---------------------------------------------------------------------------

#define N_ROWS 16384
#define DDIM   512
#define KCODES 8192

#define OFF_Q  ((size_t)0)
#define OFF_T  ((size_t)8388608)
#define OFF_L  ((size_t)8404992)
#define OFF_E  ((size_t)8404993)
#define OFF_CS ((size_t)12599297)
#define OFF_W  ((size_t)12607489)

#define MARGIN 5e-4f
#define CBUF   4

__device__ __nv_bfloat16 g_ehi[(size_t)KCODES * DDIM];
__device__ float g_enorm[KCODES];
__device__ float g_xs[N_ROWS];
__device__ int   g_idx[N_ROWS];
__device__ int   g_cand[(size_t)N_ROWS * 32];
__device__ int   g_cnt[N_ROWS];
__device__ float g_sumsq;
__device__ float g_S;

// ---------------------------------------------------------------------------
__device__ __forceinline__ uint32_t packbf2(float lo, float hi) {
    __nv_bfloat162 h = __float22bfloat162_rn(make_float2(lo, hi));
    return *reinterpret_cast<uint32_t*>(&h);
}

__device__ __forceinline__ void mma16816(float& c0, float& c1, float& c2, float& c3,
                                         uint32_t a0, uint32_t a1, uint32_t a2,
                                         uint32_t a3, uint32_t b0, uint32_t b1) {
    asm volatile(
        "mma.sync.aligned.m16n8k16.row.col.f32.bf16.bf16.f32 "
        "{%0,%1,%2,%3}, {%4,%5,%6,%7}, {%8,%9}, {%0,%1,%2,%3};"
        : "+f"(c0), "+f"(c1), "+f"(c2), "+f"(c3)
        : "r"(a0), "r"(a1), "r"(a2), "r"(a3), "r"(b0), "r"(b1));
}

__device__ __forceinline__ uint32_t smem_u32(const void* p) {
    uint32_t a;
    asm("{ .reg .u64 t; cvta.to.shared.u64 t, %1; cvt.u32.u64 %0, t; }"
        : "=r"(a) : "l"(p));
    return a;
}

__device__ __forceinline__ void ldsm_x4(uint32_t& r0, uint32_t& r1,
                                        uint32_t& r2, uint32_t& r3, uint32_t a) {
    asm volatile("ldmatrix.sync.aligned.m8n8.x4.shared.b16 {%0,%1,%2,%3}, [%4];"
                 : "=r"(r0), "=r"(r1), "=r"(r2), "=r"(r3) : "r"(a));
}

__device__ __forceinline__ void cp_async16(uint32_t dst, const void* src) {
    asm volatile("cp.async.cg.shared.global [%0], [%1], 16;"
                 :: "r"(dst), "l"(src) : "memory");
}
#define CP_COMMIT() asm volatile("cp.async.commit_group;" ::: "memory")
#define CP_WAIT1()  asm volatile("cp.async.wait_group 1;" ::: "memory")
#define CP_WAIT0()  asm volatile("cp.async.wait_group 0;" ::: "memory")

// ---------------------------------------------------------------------------
// kernel: E -> bf16 + zero candidate counters
// ---------------------------------------------------------------------------
__global__ void k_splitE(const float* __restrict__ E) {
    size_t i = (size_t)blockIdx.x * blockDim.x + threadIdx.x;
    if (i < (size_t)KCODES * DDIM) g_ehi[i] = __float2bfloat16(E[i]);
    if (i < (size_t)N_ROWS) g_cnt[i] = 0;
}

// ---------------------------------------------------------------------------
// kernel: xs in XLA:CPU vectorized-reduce order (validated bit-exact)
// ---------------------------------------------------------------------------
__global__ void k_xnorm(const float* __restrict__ X) {
    int gid = blockIdx.x * blockDim.x + threadIdx.x;
    int n = gid >> 3;
    int l = gid & 7;
    if (n >= N_ROWS) return;
    const float* xr = X + (size_t)n * DDIM;
    float a = 0.0f;
#pragma unroll 8
    for (int t = 0; t < DDIM / 8; ++t) {
        float v = xr[t * 8 + l];
        a = __fadd_rn(a, __fmul_rn(v, v));
    }
    const unsigned m = 0xffffffffu;
    float b   = __shfl_down_sync(m, a, 4);
    float tot = __fadd_rn(a, b);
    float c   = __shfl_down_sync(m, tot, 2);
    float u   = __fadd_rn(tot, c);
    float d   = __shfl_down_sync(m, u, 1);
    float xs  = __fadd_rn(u, d);
    if (l == 0) g_xs[n] = xs;
}

// ---------------------------------------------------------------------------
// kernel: ||e||^2 (validated) + zero loss accumulator
// ---------------------------------------------------------------------------
__global__ void k_enorm(const float* __restrict__ E) {
    if (blockIdx.x == 0 && threadIdx.x == 0) g_sumsq = 0.0f;
    int warp = (blockIdx.x * blockDim.x + threadIdx.x) >> 5;
    int lane = threadIdx.x & 31;
    if (warp >= KCODES) return;
    const float4* p = reinterpret_cast<const float4*>(E + (size_t)warp * DDIM);
    float s = 0.0f;
#pragma unroll
    for (int i = 0; i < 4; ++i) {
        float4 v = p[lane + 32 * i];
        s += v.x * v.x + v.y * v.y + v.z * v.z + v.w * v.w;
    }
#pragma unroll
    for (int o = 16; o > 0; o >>= 1) s += __shfl_xor_sync(0xffffffffu, s, o);
    if (lane == 0) g_enorm[warp] = s;
}

// ---------------------------------------------------------------------------
// kernel: bf16 HMMA GEMM + approximate per-row argmin + candidate capture.
// CTA = 64 X-rows x 512 thr; 16 warps as 4(M)x4(N): warp tile 16 rows x
// 32 cols. A fragment-major resident (64KB); B cp.async 3-stage 16KB ring.
// 112KB SMEM/CTA -> 2 CTAs/SM = 32 warps/SM (occ 50%).
// ---------------------------------------------------------------------------
#define SM_AF 0
#define SM_BS 65536
#define BSTG  16384
#define SMEM_HMMA (65536 + 3 * 16384)

__device__ __forceinline__ void upd_cand(float s, int col, float& rm, int& cnt,
                                         int* cc, float* cf) {
    if (s <= rm + MARGIN) {
        if (cnt == CBUF) {
            float thr = rm + MARGIN;
            int wp = 0;
#pragma unroll
            for (int i = 0; i < CBUF; ++i)
                if (cf[i] <= thr) { cc[wp] = cc[i]; cf[wp] = cf[i]; ++wp; }
            cnt = wp;
            if (cnt == CBUF) {
                int mi = 0;
#pragma unroll
                for (int i = 1; i < CBUF; ++i)
                    if (cf[i] > cf[mi]) mi = i;
                cnt = CBUF - 1;
                cc[mi] = cc[cnt]; cf[mi] = cf[cnt];
            }
        }
        cc[cnt] = col; cf[cnt] = s; ++cnt;
        if (s < rm) rm = s;
    }
}

__global__ void __launch_bounds__(512, 2) k_hmma(const float* __restrict__ X) {
    extern __shared__ __align__(16) char smem[];
    const uint32_t sb = smem_u32(smem);
    const int tid = threadIdx.x;
    const int w   = tid >> 5;
    const int l   = tid & 31;
    const int wm  = w >> 2;          // 0..3 : rows 16*wm .. 16*wm+15
    const int wn  = w & 3;           // 0..3 : cols 32*wn .. 32*wn+31
    const int m0  = blockIdx.x * 64;

    // cp.async fill of one 64-k B chunk into stage (seg%3), swizzled:
    //   dst 16B-chunk index q' = q ^ (row & 7)
    auto FILL = [&](int seg) {
        const int nt = seg >> 3, kc = seg & 7;
        const uint32_t stage = sb + SM_BS + (seg % 3) * BSTG;
        const char* srcb = reinterpret_cast<const char*>(g_ehi) +
                           (size_t)(nt * 128) * 1024 + kc * 128;
#pragma unroll
        for (int i = 0; i < 2; ++i) {
            int f = tid + 512 * i;
            int row = f >> 3, q = f & 7;
            cp_async16(stage + row * 128 + ((q ^ (row & 7)) << 4),
                       srcb + (size_t)row * 1024 + q * 16);
        }
        CP_COMMIT();
    };

    FILL(0);
    FILL(1);

    // ---- build A fragments (bf16) from fp32 X: 4 tiles of 16 rows
    for (int e = tid; e < 4096; e += 512) {
        int tw = e >> 10, rem = e & 1023, s = rem >> 5, ll = rem & 31;
        int r = m0 + tw * 16 + (ll >> 2);
        int k = s * 16 + 2 * (ll & 3);
        const float* x0 = X + (size_t)r * DDIM + k;
        float2 v00 = *reinterpret_cast<const float2*>(x0);
        float2 v10 = *reinterpret_cast<const float2*>(x0 + 8 * DDIM);
        float2 v01 = *reinterpret_cast<const float2*>(x0 + 8);
        float2 v11 = *reinterpret_cast<const float2*>(x0 + 8 * DDIM + 8);
        uint4 u;
        u.x = packbf2(v00.x, v00.y);
        u.y = packbf2(v10.x, v10.y);
        u.z = packbf2(v01.x, v01.y);
        u.w = packbf2(v11.x, v11.y);
        *reinterpret_cast<uint4*>(smem + SM_AF + (size_t)e * 16) = u;
    }

    // per-lane candidate state for 2 rows: R[b] = m0 + 16*wm + 8*b + (l>>2)
    float rm[2];
    int   cnt2[2];
    int   cc[2][CBUF];
    float cf[2][CBUF];
#pragma unroll
    for (int b = 0; b < 2; ++b) { rm[b] = __int_as_float(0x7f800000); cnt2[b] = 0; }

    // ldmatrix lane pieces (validated in R15): bt = l>>3;
    // col-in-16 = (bt>>1)*8 + (l&7); k-chunk low bit = bt&1; XOR term = l&7
    const int bt   = l >> 3;
    const int bcol = ((bt >> 1) << 3) + (l & 7);
    const int kb1  = bt & 1;
    const int l7   = l & 7;
    const uint32_t colbase = (wn * 32 + bcol) * 128;  // within stage

    float acc[4][4];

    for (int seg = 0; seg < 512; ++seg) {
        const int nt = seg >> 3, kc = seg & 7;
        if (kc == 0) {
#pragma unroll
            for (int g = 0; g < 4; ++g)
#pragma unroll
                for (int q = 0; q < 4; ++q) acc[g][q] = 0.0f;
        }

        CP_WAIT1();          // own copies of fill(seg) landed
        __syncthreads();     // cross-thread visibility; stage (seg+2)%3 free
        if (seg + 2 < 512) FILL(seg + 2);

        const uint32_t bstage = sb + SM_BS + (seg % 3) * BSTG;

#pragma unroll
        for (int s = 0; s < 4; ++s) {
            uint4 af = *reinterpret_cast<const uint4*>(
                smem + SM_AF + (size_t)((wm * 32 + (kc * 4 + s)) * 32 + l) * 16);
            const uint32_t ksw = (uint32_t)(((s << 1) | kb1) ^ l7) << 4;
            uint32_t bw[4][2];
#pragma unroll
            for (int gp = 0; gp < 2; ++gp) {
                uint32_t r0, r1, r2, r3;
                ldsm_x4(r0, r1, r2, r3, bstage + colbase + gp * (16 * 128) + ksw);
                bw[2 * gp][0] = r0; bw[2 * gp][1] = r1;
                bw[2 * gp + 1][0] = r2; bw[2 * gp + 1][1] = r3;
            }
#pragma unroll
            for (int g = 0; g < 4; ++g)
                mma16816(acc[g][0], acc[g][1], acc[g][2], acc[g][3],
                         af.x, af.y, af.z, af.w, bw[g][0], bw[g][1]);
        }

        if (kc == 7) {
            // epilogue: s~ = en - 2*dot (xs constant per row); capture
#pragma unroll
            for (int g = 0; g < 4; ++g) {
                int col0 = nt * 128 + wn * 32 + g * 8 + 2 * (l & 3);
                float2 en = __ldg(reinterpret_cast<const float2*>(g_enorm + col0));
                float s00 = fmaf(-2.0f, acc[g][0], en.x);
                float s01 = fmaf(-2.0f, acc[g][1], en.y);
                float s10 = fmaf(-2.0f, acc[g][2], en.x);
                float s11 = fmaf(-2.0f, acc[g][3], en.y);
                upd_cand(s00, col0,     rm[0], cnt2[0], cc[0], cf[0]);
                upd_cand(s01, col0 + 1, rm[0], cnt2[0], cc[0], cf[0]);
                upd_cand(s10, col0,     rm[1], cnt2[1], cc[1], cf[1]);
                upd_cand(s11, col0 + 1, rm[1], cnt2[1], cc[1], cf[1]);
            }
        }
    }
    CP_WAIT0();

    // finalize: per-row min over the 4 lanes sharing a row, filter, append
#pragma unroll
    for (int b = 0; b < 2; ++b) {
        float gm = rm[b];
        gm = fminf(gm, __shfl_xor_sync(0xffffffffu, gm, 1));
        gm = fminf(gm, __shfl_xor_sync(0xffffffffu, gm, 2));
        float thr = gm + MARGIN;
        int kept = 0, tmp[CBUF];
#pragma unroll
        for (int i = 0; i < CBUF; ++i)
            if (i < cnt2[b] && cf[b][i] <= thr) tmp[kept++] = cc[b][i];
        if (kept) {
            int row = m0 + 16 * wm + 8 * b + (l >> 2);
            int base = atomicAdd(&g_cnt[row], kept);
            for (int i = 0; i < kept; ++i)
                if (base + i < 32) g_cand[(size_t)row * 32 + base + i] = tmp[i];
        }
    }
}

// ---------------------------------------------------------------------------
// kernel: exact rescoring (R5-validated chain: sequential-k single-acc fma,
// fl(fl(xs-2dot)+en), ties -> lowest index)
// ---------------------------------------------------------------------------
__global__ void __launch_bounds__(32) k_rescore(const float* __restrict__ X,
                                                const float* __restrict__ E) {
    __shared__ float sx[DDIM];
    const int row = blockIdx.x;
    const int t   = threadIdx.x;
    const float4* xr = reinterpret_cast<const float4*>(X + (size_t)row * DDIM);
#pragma unroll
    for (int r = 0; r < 4; ++r)
        reinterpret_cast<float4*>(sx)[t + 32 * r] = xr[t + 32 * r];
    __syncwarp();

    int cnt = g_cnt[row];
    if (cnt > 32) cnt = 32;
    float s  = __int_as_float(0x7f800000);
    int  col = 0x7fffffff;
    if (t < cnt) {
        col = g_cand[(size_t)row * 32 + t];
        const float* er = E + (size_t)col * DDIM;
        float acc = 0.0f;
#pragma unroll 8
        for (int k = 0; k < DDIM; ++k) acc = __fmaf_rn(sx[k], er[k], acc);
        s = __fadd_rn(__fadd_rn(g_xs[row], -2.0f * acc), g_enorm[col]);
    }
#pragma unroll
    for (int o = 16; o > 0; o >>= 1) {
        float vs = __shfl_down_sync(0xffffffffu, s, o);
        int   vc = __shfl_down_sync(0xffffffffu, col, o);
        if (vs < s || (vs == s && vc < col)) { s = vs; col = vc; }
    }
    if (t == 0) g_idx[row] = col;
}

// ---------------------------------------------------------------------------
// EMA update kernels (validated)
// ---------------------------------------------------------------------------
__global__ void k_init(const float* __restrict__ ew,
                       const float* __restrict__ ecs,
                       float* __restrict__ out) {
    size_t i = (size_t)blockIdx.x * blockDim.x + threadIdx.x;
    if (i < (size_t)KCODES * DDIM) out[OFF_W + i] = 0.99f * ew[i];
    if (i < (size_t)KCODES)        out[OFF_CS + i] = 0.99f * ecs[i];
}

__global__ void __launch_bounds__(128)
k_gather(const float* __restrict__ X, const float* __restrict__ E,
         float* __restrict__ out) {
    const int n   = blockIdx.x;
    const int t   = threadIdx.x;
    const int idx = g_idx[n];
    const float4 f = reinterpret_cast<const float4*>(X + (size_t)n * DDIM)[t];
    const float4 e = reinterpret_cast<const float4*>(E + (size_t)idx * DDIM)[t];
    float4 q;
    q.x = f.x + (e.x - f.x);
    q.y = f.y + (e.y - f.y);
    q.z = f.z + (e.z - f.z);
    q.w = f.w + (e.w - f.w);
    reinterpret_cast<float4*>(out + OFF_Q + (size_t)n * DDIM)[t] = q;
    float dx = f.x - q.x, dy = f.y - q.y, dz = f.z - q.z, dw = f.w - q.w;
    float local = dx * dx + dy * dy + dz * dz + dw * dw;

    const float om = (float)(1.0 - 0.99);
    float* wv = out + OFF_W + (size_t)idx * DDIM + (size_t)t * 4;
    atomicAdd(wv + 0, om * f.x);
    atomicAdd(wv + 1, om * f.y);
    atomicAdd(wv + 2, om * f.z);
    atomicAdd(wv + 3, om * f.w);

    __shared__ float red[128];
    red[t] = local;
    __syncthreads();
#pragma unroll
    for (int o = 64; o > 0; o >>= 1) {
        if (t < o) red[t] += red[t + o];
        __syncthreads();
    }
    if (t == 0) {
        atomicAdd(&g_sumsq, red[0]);
        out[OFF_T + n] = (float)idx;
        atomicAdd(out + OFF_CS + idx, om);
    }
}

__global__ void k_sumcs(const float* __restrict__ cs) {
    __shared__ float red[256];
    float s = 0.0f;
    for (int i = threadIdx.x; i < KCODES; i += 256) s += cs[i];
    red[threadIdx.x] = s;
    __syncthreads();
#pragma unroll
    for (int o = 128; o > 0; o >>= 1) {
        if (threadIdx.x < o) red[threadIdx.x] += red[threadIdx.x + o];
        __syncthreads();
    }
    if (threadIdx.x == 0) g_S = red[0];
}

__global__ void k_final(float* __restrict__ out) {
    size_t i = (size_t)blockIdx.x * blockDim.x + threadIdx.x;
    if (i == 0) out[OFF_L] = 0.25f * (g_sumsq / 8388608.0f);
    if (i >= (size_t)KCODES * DDIM) return;
    size_t k = i >> 9;
    float csn = (out[OFF_CS + k] + 1e-5f) / (g_S + (float)(8192 * 1e-5));
    out[OFF_E + i] = out[OFF_W + i] / csn;
}

// ---------------------------------------------------------------------------
extern "C" void kernel_launch(void* const* d_in, const int* in_sizes, int n_in,
                              void* d_out, int out_size) {
    const float* X   = (const float*)d_in[0];
    const float* E   = (const float*)d_in[1];
    const float* ecs = (const float*)d_in[2];
    const float* ew  = (const float*)d_in[3];
    float* out = (float*)d_out;

    cudaFuncSetAttribute(k_hmma, cudaFuncAttributeMaxDynamicSharedMemorySize,
                         SMEM_HMMA);

    k_splitE <<<(KCODES * DDIM + 255) / 256, 256>>>(E);
    k_xnorm  <<<N_ROWS * 8 / 256, 256>>>(X);
    k_enorm  <<<KCODES / 8, 256>>>(E);
    k_hmma   <<<N_ROWS / 64, 512, SMEM_HMMA>>>(X);
    k_rescore<<<N_ROWS, 32>>>(X, E);
    k_init   <<<(KCODES * DDIM + 255) / 256, 256>>>(ew, ecs, out);
    k_gather <<<N_ROWS, 128>>>(X, E, out);
    k_sumcs  <<<1, 256>>>(out + OFF_CS);
    k_final  <<<(KCODES * DDIM + 255) / 256, 256>>>(out);
}